// round 9
// baseline (speedup 1.0000x reference)
#include <cuda_runtime.h>
#include <cstdint>

// s1, blur: [4, 10, 256, 256] fp32 -> out: [4, 256, 256] fp32.
//
// Per pixel: candidate i (0..10): x_j = s_j + b_j (j<i) else s_j - b_j.
// argmin_i std(x); output mean of winner.
// Identity: argmin variance == argmin( 4*P_i - sum_i^2/n ),
//   P_i = prefix sum s_j*b_j ; sum_i = (S-B) + 2*prefix sum b_j.
//
// Final form: LDG.128 (fewest load instructions; best timed result) combined
// with the L2::256B fetch-granule hint (best cold-DRAM result). 512 CTAs x
// 128 threads for smooth per-SM balance. Timed runs are pinned at the
// ~6.6us harness floor across all 7 prior designs; this maximizes margin
// under that floor in both warm and cold regimes.

#define NPLANES 10
#define HW4     16384   // (256*256)/4 quads per plane

__device__ __forceinline__ float4 ldg_nc_256(const float4* p) {
    float4 r;
    asm volatile("ld.global.nc.L2::256B.v4.f32 {%0, %1, %2, %3}, [%4];"
                 : "=f"(r.x), "=f"(r.y), "=f"(r.z), "=f"(r.w) : "l"(p));
    return r;
}

__global__ __launch_bounds__(128)
void distregression_kernel(const float4* __restrict__ s1,
                           const float4* __restrict__ blur,
                           float4* __restrict__ out,
                           int nquads)
{
    int t = blockIdx.x * blockDim.x + threadIdx.x;
    if (t >= nquads) return;

    int b   = t >> 14;            // quad / HW4 -> batch
    int hw4 = t & (HW4 - 1);

    const float4* s1p = s1   + (size_t)b * NPLANES * HW4 + hw4;
    const float4* blp = blur + (size_t)b * NPLANES * HW4 + hw4;

    // Front-batch all 20 LDG.128 (MLP=20, 256B L2 fetch granule).
    float sv[NPLANES][4], bv[NPLANES][4];
    #pragma unroll
    for (int j = 0; j < NPLANES; j++) {
        float4 s = ldg_nc_256(s1p + j * HW4);
        float4 v = ldg_nc_256(blp + j * HW4);
        sv[j][0] = s.x; sv[j][1] = s.y; sv[j][2] = s.z; sv[j][3] = s.w;
        bv[j][0] = v.x; bv[j][1] = v.y; bv[j][2] = v.z; bv[j][3] = v.w;
    }

    const float inv_n = 1.0f / NPLANES;
    float res[4];
    #pragma unroll
    for (int k = 0; k < 4; k++) {
        float S = 0.f, B = 0.f;
        #pragma unroll
        for (int j = 0; j < NPLANES; j++) {
            S += sv[j][k];
            B += bv[j][k];
        }

        float sum = S - B;      // candidate 0: all lo
        float P   = 0.f;        // prefix sum of s_j*b_j
        float bestM = 3.0e38f, bestSum = sum;

        #pragma unroll
        for (int i = 0; i <= NPLANES; i++) {
            float M = fmaf(-sum * inv_n, sum, 4.0f * P);
            if (M < bestM) { bestM = M; bestSum = sum; }   // first index wins ties
            if (i < NPLANES) {
                sum = fmaf(2.0f, bv[i][k], sum);
                P   = fmaf(sv[i][k], bv[i][k], P);
            }
        }
        res[k] = bestSum * inv_n;
    }

    out[t] = make_float4(res[0], res[1], res[2], res[3]);
}

extern "C" void kernel_launch(void* const* d_in, const int* in_sizes, int n_in,
                              void* d_out, int out_size)
{
    const float4* s1   = (const float4*)d_in[0];
    const float4* blur = (const float4*)d_in[1];
    float4* out = (float4*)d_out;

    int nquads  = out_size / 4;                      // 65536
    int threads = 128;
    int blocks  = (nquads + threads - 1) / threads;  // 512
    distregression_kernel<<<blocks, threads>>>(s1, blur, out, nquads);
}